// round 3
// baseline (speedup 1.0000x reference)
#include <cuda_runtime.h>
#include <cstdint>

// Problem constants (fixed by the reference setup)
#define NN   50000
#define EE   1000000
#define BB   2048
#define RR   3
#define INP  256
#define HID  512
#define OUTC 256
#define BN_EPS 1e-5f

// ---------------- device scratch (no allocations allowed) ----------------
__device__ int   g_pos[NN];        // node id -> batch position, -1 otherwise
__device__ int   g_bn[BB];         // batch node ids as int
__device__ int   g_appear[BB];     // appear flag per batch position
__device__ int   g_rank[BB];       // appearance rank per batch position
__device__ __align__(16) float g_deg[BB];
__device__ __align__(16) float g_dinv[BB];
__device__ int   g_kept;
__device__ int   g_ks[EE];
__device__ int   g_kd[EE];
__device__ __align__(16) float g_XW[BB * HID];
__device__ __align__(16) float g_AGG[BB * HID];
__device__ __align__(16) float g_H[BB * HID];
__device__ __align__(16) float g_HW[BB * OUTC];
__device__ __align__(16) float g_sum[HID];
__device__ __align__(16) float g_sumsq[HID];
__device__ __align__(16) float g_scale[HID];
__device__ __align__(16) float g_shift[HID];

// ---------------- setup kernels ----------------
__global__ void k_init_pos() {
    int i = blockIdx.x * blockDim.x + threadIdx.x;
    if (i < NN) g_pos[i] = -1;
}

__global__ void k_set_pos(const int* __restrict__ bn) {
    int i = blockIdx.x * blockDim.x + threadIdx.x;
    if (i < BB) {
        int v = bn[i];
        g_pos[v] = i;
        g_bn[i] = v;
    }
}

__global__ void k_clear_rel() {
    int i = blockIdx.x * blockDim.x + threadIdx.x;
    if (i < BB) { g_appear[i] = 0; g_deg[i] = 1.0f; }
    if (i < HID) { g_sum[i] = 0.0f; g_sumsq[i] = 0.0f; }
    if (i == 0) g_kept = 0;
}

// ---------------- edge filtering (edge_index is int32) ----------------
__global__ void k_scan(const int* __restrict__ src,
                       const int* __restrict__ dst) {
    int stride = gridDim.x * blockDim.x;
    for (int e = blockIdx.x * blockDim.x + threadIdx.x; e < EE; e += stride) {
        int ps = g_pos[src[e]];
        int pd = g_pos[dst[e]];
        if ((ps | pd) >= 0) {  // both >= 0
            g_appear[ps] = 1;
            g_appear[pd] = 1;
            int ix = atomicAdd(&g_kept, 1);
            g_ks[ix] = ps;
            g_kd[ix] = pd;
        }
    }
}

// single block, 256 threads, 8 elements each: inclusive prefix -> rank
__global__ void k_prefix() {
    __shared__ int ssum[256];
    int t = threadIdx.x;
    int base = t * 8;
    int v[8];
    int run = 0;
#pragma unroll
    for (int j = 0; j < 8; j++) { run += g_appear[base + j]; v[j] = run; }
    ssum[t] = run;
    __syncthreads();
    for (int off = 1; off < 256; off <<= 1) {
        int x = (t >= off) ? ssum[t - off] : 0;
        __syncthreads();
        ssum[t] += x;
        __syncthreads();
    }
    int pre = (t > 0) ? ssum[t - 1] : 0;
#pragma unroll
    for (int j = 0; j < 8; j++) g_rank[base + j] = pre + v[j] - 1;
}

__global__ void k_renum_deg() {
    int ne = g_kept;
    int stride = gridDim.x * blockDim.x;
    for (int e = blockIdx.x * blockDim.x + threadIdx.x; e < ne; e += stride) {
        int rs = g_rank[g_ks[e]];
        int rd = g_rank[g_kd[e]];
        g_ks[e] = rs;
        g_kd[e] = rd;
        atomicAdd(&g_deg[rd], 1.0f);
    }
}

__global__ void k_dinv() {
    int i = blockIdx.x * blockDim.x + threadIdx.x;
    if (i < BB) g_dinv[i] = rsqrtf(g_deg[i]);
}

// ---------------- SGEMM core: C[M,N] = A[M,K] @ B[K,N] ------------------
// Tile 64x64x16, 256 threads, 4x4 per thread. A row indices optionally
// gathered through g_bn (for the feature gather in GEMM1).
template <int K, int N, bool GATHER>
__device__ __forceinline__ void sgemm_body(const float* __restrict__ A,
                                           const float* __restrict__ B,
                                           float* __restrict__ C) {
    __shared__ float As[16][64];
    __shared__ float Bs[16][64];
    const int tid = threadIdx.x;
    const int arow = tid >> 2, acol = (tid & 3) << 2;
    const int brow = tid >> 4, bcol = (tid & 15) << 2;
    const int tx = tid & 15, ty = tid >> 4;
    const int m0 = blockIdx.y * 64, n0 = blockIdx.x * 64;

    int gm = m0 + arow;
    int grow = GATHER ? g_bn[gm] : gm;
    const float* arowp = A + (size_t)grow * K;

    float acc[4][4];
#pragma unroll
    for (int i = 0; i < 4; i++)
#pragma unroll
        for (int j = 0; j < 4; j++) acc[i][j] = 0.0f;

    for (int k0 = 0; k0 < K; k0 += 16) {
        float4 av = *(const float4*)(arowp + k0 + acol);
        As[acol + 0][arow] = av.x;
        As[acol + 1][arow] = av.y;
        As[acol + 2][arow] = av.z;
        As[acol + 3][arow] = av.w;
        *(float4*)(&Bs[brow][bcol]) =
            *(const float4*)(B + (size_t)(k0 + brow) * N + n0 + bcol);
        __syncthreads();
#pragma unroll
        for (int k = 0; k < 16; k++) {
            float4 a4 = *(const float4*)(&As[k][ty << 2]);
            float4 b4 = *(const float4*)(&Bs[k][tx << 2]);
            float ar[4] = {a4.x, a4.y, a4.z, a4.w};
            float br[4] = {b4.x, b4.y, b4.z, b4.w};
#pragma unroll
            for (int i = 0; i < 4; i++)
#pragma unroll
                for (int j = 0; j < 4; j++) acc[i][j] += ar[i] * br[j];
        }
        __syncthreads();
    }
#pragma unroll
    for (int i = 0; i < 4; i++) {
        float4 o = make_float4(acc[i][0], acc[i][1], acc[i][2], acc[i][3]);
        *(float4*)(C + (size_t)(m0 + (ty << 2) + i) * N + n0 + (tx << 2)) = o;
    }
}

// GEMM1: gather(features via g_bn) @ W1 -> g_XW  [2048,512], K=256
__global__ void __launch_bounds__(256)
k_sgemm1(const float* __restrict__ feat, const float* __restrict__ W1) {
    sgemm_body<INP, HID, true>(feat, W1, g_XW);
}

// GEMM2: g_H @ W2 -> g_HW  [2048,256], K=512
__global__ void __launch_bounds__(256)
k_sgemm2(const float* __restrict__ W2) {
    sgemm_body<HID, OUTC, false>(g_H, W2, g_HW);
}

// ---------------- aggregation ----------------
// AGG = dinv^2 * XW  (self-loop term)
__global__ void k_agg_init() {
    int idx = blockIdx.x * blockDim.x + threadIdx.x;  // BB*HID threads
    int i = idx >> 9;
    float dv = g_dinv[i];
    g_AGG[idx] = dv * dv * g_XW[idx];
}

// edge scatter for layer 1: g_AGG[d] += dinv[s]*dinv[d]*g_XW[s]
__global__ void k_agg_edges_h() {
    int ne = g_kept;
    for (int e = blockIdx.x; e < ne; e += gridDim.x) {
        int s = g_ks[e], d = g_kd[e];
        float coeff = g_dinv[s] * g_dinv[d];
        const float* sp = g_XW + (size_t)s * HID;
        float* dp = g_AGG + (size_t)d * HID;
        for (int c = threadIdx.x; c < HID; c += blockDim.x)
            atomicAdd(&dp[c], coeff * sp[c]);
    }
}

// edge scatter for layer 2: out[d] += dinv[s]*dinv[d]*g_HW[s]
__global__ void k_agg_edges_o(float* __restrict__ outp) {
    int ne = g_kept;
    for (int e = blockIdx.x; e < ne; e += gridDim.x) {
        int s = g_ks[e], d = g_kd[e];
        float coeff = g_dinv[s] * g_dinv[d];
        const float* sp = g_HW + (size_t)s * OUTC;
        float* dp = outp + (size_t)d * OUTC;
        for (int c = threadIdx.x; c < OUTC; c += blockDim.x)
            atomicAdd(&dp[c], coeff * sp[c]);
    }
}

// ---------------- batchnorm ----------------
__global__ void k_bn_stats() {
    int c = threadIdx.x;  // 512 threads
    int r0 = blockIdx.x * 32;
    float s = 0.0f, s2 = 0.0f;
#pragma unroll 4
    for (int i = 0; i < 32; i++) {
        float v = g_AGG[(size_t)(r0 + i) * HID + c];
        s += v;
        s2 += v * v;
    }
    atomicAdd(&g_sum[c], s);
    atomicAdd(&g_sumsq[c], s2);
}

__global__ void k_bn_final(const float* __restrict__ gamma,
                           const float* __restrict__ beta) {
    int c = threadIdx.x;
    float inv = 1.0f / (float)BB;
    float mu = g_sum[c] * inv;
    float var = g_sumsq[c] * inv - mu * mu;
    float sc = rsqrtf(var + BN_EPS) * gamma[c];
    g_scale[c] = sc;
    g_shift[c] = beta[c] - mu * sc;
}

__global__ void k_bn_norm() {
    int idx = blockIdx.x * blockDim.x + threadIdx.x;  // BB*HID threads
    int c = idx & (HID - 1);
    g_H[idx] = g_AGG[idx] * g_scale[c] + g_shift[c];
}

// ---------------- output init (self-loop + bias) ----------------
__global__ void k_out_init(float* __restrict__ outp, const float* __restrict__ b2) {
    int idx = blockIdx.x * blockDim.x + threadIdx.x;  // BB*OUTC threads
    int i = idx >> 8;
    int c = idx & (OUTC - 1);
    float dv = g_dinv[i];
    outp[idx] = dv * dv * g_HW[idx] + b2[c];
}

// ---------------- host launch ----------------
extern "C" void kernel_launch(void* const* d_in, const int* in_sizes, int n_in,
                              void* d_out, int out_size) {
    const float* feat = (const float*)d_in[0];
    const float* W1 = (const float*)d_in[1];
    // b1 (d_in[2]) cancels inside BatchNorm -> unused
    const float* W2 = (const float*)d_in[3];
    const float* b2 = (const float*)d_in[4];
    const float* gamma = (const float*)d_in[5];
    const float* beta = (const float*)d_in[6];
    const int* ei = (const int*)d_in[7];      // int32 (JAX x64 disabled)
    const int* bn = (const int*)d_in[8];      // int32
    float* out = (float*)d_out;

    k_init_pos<<<(NN + 255) / 256, 256>>>();
    k_set_pos<<<(BB + 255) / 256, 256>>>(bn);

    for (int r = 0; r < RR; r++) {
        const int* src = ei + (size_t)r * 2 * EE;
        const int* dst = src + EE;
        float* outp = out + (size_t)r * BB * OUTC;

        k_clear_rel<<<8, 256>>>();
        k_scan<<<2048, 256>>>(src, dst);
        k_prefix<<<1, 256>>>();
        k_renum_deg<<<256, 256>>>();
        k_dinv<<<8, 256>>>();

        {
            dim3 grid(HID / 64, BB / 64);
            k_sgemm1<<<grid, 256>>>(feat + (size_t)r * NN * INP, W1);
        }
        k_agg_init<<<BB * HID / 256, 256>>>();
        k_agg_edges_h<<<1024, 128>>>();

        k_bn_stats<<<BB / 32, HID>>>();
        k_bn_final<<<1, HID>>>(gamma, beta);
        k_bn_norm<<<BB * HID / 256, 256>>>();

        {
            dim3 grid(OUTC / 64, BB / 64);
            k_sgemm2<<<grid, 256>>>(W2);
        }
        k_out_init<<<BB * OUTC / 256, 256>>>(outp, b2);
        k_agg_edges_o<<<1024, 128>>>(outp);
    }
}

// round 5
// speedup vs baseline: 1.0597x; 1.0597x over previous
#include <cuda_runtime.h>
#include <cuda_bf16.h>
#include <cstdint>

#define NN   50000
#define EE   1000000
#define BB   2048
#define RR   3
#define INP  256
#define HID  512
#define OUTC 256
#define BN_EPS 1e-5f
#define K3_1 (3*INP)    // 768  (hi,lo,hi split of K=256)
#define K3_2 (3*HID)    // 1536 (hi,lo,hi split of K=512)

// ---------------- device scratch ----------------
__device__ int   g_pos[NN];
__device__ int   g_bn[BB];
__device__ int   g_appear[BB];
__device__ int   g_rank[BB];
__device__ float g_deg[BB];
__device__ float g_dinv[BB];
__device__ int   g_kept;
__device__ int   g_ks[EE];
__device__ int   g_kd[EE];
__device__ __align__(16) __nv_bfloat16 g_A1[BB * K3_1];    // split features
__device__ __align__(16) __nv_bfloat16 g_B1[HID * K3_1];   // split W1^T
__device__ __align__(16) __nv_bfloat16 g_A2[BB * K3_2];    // split BN(H)
__device__ __align__(16) __nv_bfloat16 g_B2[OUTC * K3_2];  // split W2^T
__device__ __align__(16) float g_XW[BB * HID];
__device__ __align__(16) float g_AGG[BB * HID];
__device__ __align__(16) float g_HW[BB * OUTC];
__device__ float g_sum[HID];
__device__ float g_sumsq[HID];
__device__ float g_scale[HID];
__device__ float g_shift[HID];

// ---------------- helpers ----------------
__device__ __forceinline__ uint32_t smem_u32(const void* p) {
    uint32_t a;
    asm("{ .reg .u64 t; cvta.to.shared.u64 t, %1; cvt.u32.u64 %0, t; }"
        : "=r"(a) : "l"(p));
    return a;
}
__device__ __forceinline__ void ldsm_x4(uint32_t& r0, uint32_t& r1,
                                        uint32_t& r2, uint32_t& r3, uint32_t a) {
    asm volatile("ldmatrix.sync.aligned.m8n8.x4.shared.b16 {%0,%1,%2,%3}, [%4];"
                 : "=r"(r0), "=r"(r1), "=r"(r2), "=r"(r3) : "r"(a));
}
__device__ __forceinline__ void mma16816(float* d, const uint32_t* a,
                                         const uint32_t* b) {
    asm volatile(
        "mma.sync.aligned.m16n8k16.row.col.f32.bf16.bf16.f32 "
        "{%0,%1,%2,%3}, {%4,%5,%6,%7}, {%8,%9}, {%0,%1,%2,%3};"
        : "+f"(d[0]), "+f"(d[1]), "+f"(d[2]), "+f"(d[3])
        : "r"(a[0]), "r"(a[1]), "r"(a[2]), "r"(a[3]), "r"(b[0]), "r"(b[1]));
}

// ---------------- setup ----------------
__global__ void k_init_pos() {
    int i = blockIdx.x * blockDim.x + threadIdx.x;
    if (i < NN) g_pos[i] = -1;
}
__global__ void k_set_pos(const int* __restrict__ bn) {
    int i = blockIdx.x * blockDim.x + threadIdx.x;
    if (i < BB) { int v = bn[i]; g_pos[v] = i; g_bn[i] = v; }
}
__global__ void k_clear_rel() {
    int i = blockIdx.x * blockDim.x + threadIdx.x;
    if (i < BB) { g_appear[i] = 0; g_deg[i] = 1.0f; }
    if (i < HID) { g_sum[i] = 0.0f; g_sumsq[i] = 0.0f; }
    if (i == 0) g_kept = 0;
}

// ---------------- edge filtering (int4-vectorized) ----------------
__global__ void k_scan(const int4* __restrict__ src4, const int4* __restrict__ dst4) {
    int i = blockIdx.x * blockDim.x + threadIdx.x;
    if (i >= EE / 4) return;
    int4 s = src4[i], d = dst4[i];
    int ss[4] = {s.x, s.y, s.z, s.w};
    int dd[4] = {d.x, d.y, d.z, d.w};
#pragma unroll
    for (int j = 0; j < 4; j++) {
        int ps = g_pos[ss[j]];
        int pd = g_pos[dd[j]];
        if ((ps | pd) >= 0) {
            g_appear[ps] = 1;
            g_appear[pd] = 1;
            int ix = atomicAdd(&g_kept, 1);
            g_ks[ix] = ps;
            g_kd[ix] = pd;
        }
    }
}

__global__ void k_prefix() {
    __shared__ int ssum[256];
    int t = threadIdx.x;
    int base = t * 8;
    int v[8];
    int run = 0;
#pragma unroll
    for (int j = 0; j < 8; j++) { run += g_appear[base + j]; v[j] = run; }
    ssum[t] = run;
    __syncthreads();
    for (int off = 1; off < 256; off <<= 1) {
        int x = (t >= off) ? ssum[t - off] : 0;
        __syncthreads();
        ssum[t] += x;
        __syncthreads();
    }
    int pre = (t > 0) ? ssum[t - 1] : 0;
#pragma unroll
    for (int j = 0; j < 8; j++) g_rank[base + j] = pre + v[j] - 1;
}

__global__ void k_renum_deg() {
    int ne = g_kept;
    int stride = gridDim.x * blockDim.x;
    for (int e = blockIdx.x * blockDim.x + threadIdx.x; e < ne; e += stride) {
        int rs = g_rank[g_ks[e]];
        int rd = g_rank[g_kd[e]];
        g_ks[e] = rs;
        g_kd[e] = rd;
        atomicAdd(&g_deg[rd], 1.0f);
    }
}
__global__ void k_dinv() {
    int i = blockIdx.x * blockDim.x + threadIdx.x;
    if (i < BB) g_dinv[i] = rsqrtf(g_deg[i]);
}

// ---------------- bf16 split conversions ----------------
__device__ __forceinline__ void split2(float x, __nv_bfloat16& hi, __nv_bfloat16& lo) {
    hi = __float2bfloat16(x);
    lo = __float2bfloat16(x - __bfloat162float(hi));
}

__global__ void k_conv_feat(const float* __restrict__ feat) {
    int idx = blockIdx.x * blockDim.x + threadIdx.x;  // BB*INP
    int i = idx >> 8, c = idx & (INP - 1);
    float x = feat[(size_t)g_bn[i] * INP + c];
    __nv_bfloat16 hi, lo; split2(x, hi, lo);
    size_t base = (size_t)i * K3_1;
    g_A1[base + c] = hi;
    g_A1[base + INP + c] = lo;
    g_A1[base + 2 * INP + c] = hi;
}

__global__ void k_convW1(const float* __restrict__ W1) {
    int idx = blockIdx.x * blockDim.x + threadIdx.x;  // HID*INP
    int n = idx >> 8, k = idx & (INP - 1);
    float x = W1[(size_t)k * HID + n];
    __nv_bfloat16 hi, lo; split2(x, hi, lo);
    size_t base = (size_t)n * K3_1;
    g_B1[base + k] = hi;
    g_B1[base + INP + k] = hi;
    g_B1[base + 2 * INP + k] = lo;
}

__global__ void k_convW2(const float* __restrict__ W2) {
    int idx = blockIdx.x * blockDim.x + threadIdx.x;  // OUTC*HID
    int n = idx >> 9, k = idx & (HID - 1);
    float x = W2[(size_t)k * OUTC + n];
    __nv_bfloat16 hi, lo; split2(x, hi, lo);
    size_t base = (size_t)n * K3_2;
    g_B2[base + k] = hi;
    g_B2[base + HID + k] = hi;
    g_B2[base + 2 * HID + k] = lo;
}

// BN normalize fused into split conversion
__global__ void k_bn_norm_conv() {
    int idx = blockIdx.x * blockDim.x + threadIdx.x;  // BB*HID
    int i = idx >> 9, c = idx & (HID - 1);
    float h = g_AGG[idx] * g_scale[c] + g_shift[c];
    __nv_bfloat16 hi, lo; split2(h, hi, lo);
    size_t base = (size_t)i * K3_2;
    g_A2[base + c] = hi;
    g_A2[base + HID + c] = lo;
    g_A2[base + 2 * HID + c] = hi;
}

// ---------------- HMMA GEMM: C = A[M,K3] @ BT[N,K3]^T -------------------
// CTA tile 128 x NTILE, 8 warps (4 along M, 2 along N). Warp tile 32 x NTILE/2.
// K chunks of 64 via SW128-swizzled smem; fragments via ldmatrix.x4.
// EPI=0: writes g_XW and g_AGG = dinv^2*XW.  EPI=1: writes g_HW and out+=bias form.
template <int K3, int NTOT, int NTILE, int EPI>
__device__ __forceinline__ void hmma_body(const __nv_bfloat16* __restrict__ A,
                                          const __nv_bfloat16* __restrict__ BT,
                                          float* __restrict__ outp,
                                          const float* __restrict__ b2) {
    constexpr int NW = NTILE / 2;   // per n-warp columns
    constexpr int NF = NW / 8;      // n8 fragments per warp
    __shared__ alignas(1024) __nv_bfloat16 sA[128 * 64];
    __shared__ alignas(1024) __nv_bfloat16 sB[NTILE * 64];

    const int tid = threadIdx.x, wid = tid >> 5, lid = tid & 31;
    const int mwarp = wid & 3, nwarp = wid >> 2;
    const int m0 = blockIdx.y * 128, n0 = blockIdx.x * NTILE;
    const uint32_t sA0 = smem_u32(sA), sB0 = smem_u32(sB);

    float acc[2][NF][4];
#pragma unroll
    for (int mi = 0; mi < 2; mi++)
#pragma unroll
        for (int nf = 0; nf < NF; nf++)
#pragma unroll
            for (int j = 0; j < 4; j++) acc[mi][nf][j] = 0.0f;

    // per-lane ldmatrix address components
    const int a_row = lid & 15, a_kb = (lid >> 4) * 16;
    const int b_nn = ((lid >> 4) << 3) + (lid & 7), b_kb = ((lid >> 3) & 1) * 16;

    for (int kc = 0; kc < K3; kc += 64) {
        // stage A (16KB) and B (NTILE*128B) into swizzled smem
#pragma unroll
        for (int it = 0; it < 4; it++) {
            int idx = it * 256 + tid;
            int r = idx >> 3, c16 = idx & 7;
            uint32_t byte = (uint32_t)(r * 128 + c16 * 16);
            uint32_t sw = byte ^ ((byte >> 3) & 0x70);
            *(uint4*)((char*)sA + sw) =
                *(const uint4*)(A + (size_t)(m0 + r) * K3 + kc + c16 * 8);
        }
#pragma unroll
        for (int it = 0; it < NTILE / 32; it++) {
            int idx = it * 256 + tid;
            int r = idx >> 3, c16 = idx & 7;
            uint32_t byte = (uint32_t)(r * 128 + c16 * 16);
            uint32_t sw = byte ^ ((byte >> 3) & 0x70);
            *(uint4*)((char*)sB + sw) =
                *(const uint4*)(BT + (size_t)(n0 + r) * K3 + kc + c16 * 8);
        }
        __syncthreads();
#pragma unroll
        for (int ks = 0; ks < 4; ks++) {
            const int kbyte = ks * 32;
            uint32_t af[2][4];
#pragma unroll
            for (int mi = 0; mi < 2; mi++) {
                int row = mwarp * 32 + mi * 16 + a_row;
                uint32_t byte = (uint32_t)(row * 128 + kbyte + a_kb);
                uint32_t sw = byte ^ ((byte >> 3) & 0x70);
                ldsm_x4(af[mi][0], af[mi][1], af[mi][2], af[mi][3], sA0 + sw);
            }
            uint32_t bf_[NF][2];
#pragma unroll
            for (int np = 0; np < NF / 2; np++) {
                int nn = nwarp * NW + np * 16 + b_nn;
                uint32_t byte = (uint32_t)(nn * 128 + kbyte + b_kb);
                uint32_t sw = byte ^ ((byte >> 3) & 0x70);
                uint32_t r0, r1, r2, r3;
                ldsm_x4(r0, r1, r2, r3, sB0 + sw);
                bf_[2 * np][0] = r0; bf_[2 * np][1] = r1;
                bf_[2 * np + 1][0] = r2; bf_[2 * np + 1][1] = r3;
            }
#pragma unroll
            for (int mi = 0; mi < 2; mi++)
#pragma unroll
                for (int nf = 0; nf < NF; nf++)
                    mma16816(acc[mi][nf], af[mi], bf_[nf]);
        }
        __syncthreads();
    }

    // epilogue: D frag -> thread (row = gid, gid+8; col = tg*2, +1)
    const int gid = lid >> 2, tg = lid & 3;
#pragma unroll
    for (int mi = 0; mi < 2; mi++) {
        const int rA = m0 + mwarp * 32 + mi * 16 + gid;
        const int rB = rA + 8;
        const float dA = g_dinv[rA], dB = g_dinv[rB];
        const float d2A = dA * dA, d2B = dB * dB;
#pragma unroll
        for (int nf = 0; nf < NF; nf++) {
            const int c = n0 + nwarp * NW + nf * 8 + tg * 2;
            float2 vA = make_float2(acc[mi][nf][0], acc[mi][nf][1]);
            float2 vB = make_float2(acc[mi][nf][2], acc[mi][nf][3]);
            if (EPI == 0) {
                *(float2*)(g_XW + (size_t)rA * NTOT + c) = vA;
                *(float2*)(g_XW + (size_t)rB * NTOT + c) = vB;
                *(float2*)(g_AGG + (size_t)rA * NTOT + c) =
                    make_float2(d2A * vA.x, d2A * vA.y);
                *(float2*)(g_AGG + (size_t)rB * NTOT + c) =
                    make_float2(d2B * vB.x, d2B * vB.y);
            } else {
                *(float2*)(g_HW + (size_t)rA * NTOT + c) = vA;
                *(float2*)(g_HW + (size_t)rB * NTOT + c) = vB;
                float2 bb = *(const float2*)(b2 + c);
                *(float2*)(outp + (size_t)rA * NTOT + c) =
                    make_float2(d2A * vA.x + bb.x, d2A * vA.y + bb.y);
                *(float2*)(outp + (size_t)rB * NTOT + c) =
                    make_float2(d2B * vB.x + bb.x, d2B * vB.y + bb.y);
            }
        }
    }
}

__global__ void __launch_bounds__(256)
k_mma1() { hmma_body<K3_1, HID, 128, 0>(g_A1, g_B1, nullptr, nullptr); }

__global__ void __launch_bounds__(256)
k_mma2(float* __restrict__ outp, const float* __restrict__ b2) {
    hmma_body<K3_2, OUTC, 64, 1>(g_A2, g_B2, outp, b2);
}

// ---------------- edge scatter ----------------
__global__ void k_agg_edges_h() {
    int ne = g_kept;
    for (int e = blockIdx.x; e < ne; e += gridDim.x) {
        int s = g_ks[e], d = g_kd[e];
        float coeff = g_dinv[s] * g_dinv[d];
        const float* sp = g_XW + (size_t)s * HID;
        float* dp = g_AGG + (size_t)d * HID;
        for (int c = threadIdx.x; c < HID; c += blockDim.x)
            atomicAdd(&dp[c], coeff * sp[c]);
    }
}
__global__ void k_agg_edges_o(float* __restrict__ outp) {
    int ne = g_kept;
    for (int e = blockIdx.x; e < ne; e += gridDim.x) {
        int s = g_ks[e], d = g_kd[e];
        float coeff = g_dinv[s] * g_dinv[d];
        const float* sp = g_HW + (size_t)s * OUTC;
        float* dp = outp + (size_t)d * OUTC;
        for (int c = threadIdx.x; c < OUTC; c += blockDim.x)
            atomicAdd(&dp[c], coeff * sp[c]);
    }
}

// ---------------- batchnorm ----------------
__global__ void k_bn_stats() {
    int c = threadIdx.x;  // 512 threads
    int r0 = blockIdx.x * 32;
    float s = 0.0f, s2 = 0.0f;
#pragma unroll 4
    for (int i = 0; i < 32; i++) {
        float v = g_AGG[(size_t)(r0 + i) * HID + c];
        s += v;
        s2 += v * v;
    }
    atomicAdd(&g_sum[c], s);
    atomicAdd(&g_sumsq[c], s2);
}
__global__ void k_bn_final(const float* __restrict__ gamma,
                           const float* __restrict__ beta) {
    int c = threadIdx.x;
    float inv = 1.0f / (float)BB;
    float mu = g_sum[c] * inv;
    float var = g_sumsq[c] * inv - mu * mu;
    float sc = rsqrtf(var + BN_EPS) * gamma[c];
    g_scale[c] = sc;
    g_shift[c] = beta[c] - mu * sc;
}

// ---------------- host launch ----------------
extern "C" void kernel_launch(void* const* d_in, const int* in_sizes, int n_in,
                              void* d_out, int out_size) {
    const float* feat = (const float*)d_in[0];
    const float* W1 = (const float*)d_in[1];
    // b1 (d_in[2]) cancels inside BatchNorm -> unused
    const float* W2 = (const float*)d_in[3];
    const float* b2 = (const float*)d_in[4];
    const float* gamma = (const float*)d_in[5];
    const float* beta = (const float*)d_in[6];
    const int* ei = (const int*)d_in[7];
    const int* bn = (const int*)d_in[8];
    float* out = (float*)d_out;

    k_init_pos<<<(NN + 255) / 256, 256>>>();
    k_set_pos<<<(BB + 255) / 256, 256>>>(bn);
    k_convW1<<<HID * INP / 256, 256>>>(W1);
    k_convW2<<<OUTC * HID / 256, 256>>>(W2);

    for (int r = 0; r < RR; r++) {
        const int* src = ei + (size_t)r * 2 * EE;
        const int* dst = src + EE;
        float* outp = out + (size_t)r * BB * OUTC;

        k_clear_rel<<<8, 256>>>();
        k_scan<<<(EE / 4 + 255) / 256, 256>>>((const int4*)src, (const int4*)dst);
        k_prefix<<<1, 256>>>();
        k_renum_deg<<<256, 256>>>();
        k_dinv<<<8, 256>>>();
        k_conv_feat<<<BB * INP / 256, 256>>>(feat + (size_t)r * NN * INP);

        { dim3 grid(HID / 128, BB / 128); k_mma1<<<grid, 256>>>(); }
        k_agg_edges_h<<<1024, 128>>>();

        k_bn_stats<<<BB / 32, HID>>>();
        k_bn_final<<<1, HID>>>(gamma, beta);
        k_bn_norm_conv<<<BB * HID / 256, 256>>>();

        { dim3 grid(OUTC / 64, BB / 128); k_mma2<<<grid, 256>>>(outp, b2); }
        k_agg_edges_o<<<1024, 128>>>(outp);
    }
}

// round 6
// speedup vs baseline: 2.0850x; 1.9675x over previous
#include <cuda_runtime.h>
#include <cuda_bf16.h>
#include <cstdint>

#define NN   50000
#define EE   1000000
#define BB   2048
#define RR   3
#define INP  256
#define HID  512
#define OUTC 256
#define BN_EPS 1e-5f
#define K3_1 (3*INP)    // 768  (hi,lo,hi split of K=256)
#define K3_2 (3*HID)    // 1536 (hi,lo,hi split of K=512)

// ---------------- device scratch (all batched over RR) ----------------
__device__ int   g_pos[NN];
__device__ int   g_bn[BB];
__device__ int   g_appear[RR][BB];
__device__ int   g_rank[RR][BB];
__device__ float g_deg[RR][BB];
__device__ int   g_kept[RR];
__device__ int   g_ks[RR][EE];
__device__ int   g_kd[RR][EE];
__device__ __align__(16) __nv_bfloat16 g_A1[RR * BB * K3_1];
__device__ __align__(16) __nv_bfloat16 g_B1[HID * K3_1];
__device__ __align__(16) __nv_bfloat16 g_A2[RR * BB * K3_2];
__device__ __align__(16) __nv_bfloat16 g_B2[OUTC * K3_2];
__device__ __align__(16) float g_XW[RR * BB * HID];
__device__ __align__(16) float g_AGG[RR * BB * HID];
__device__ __align__(16) float g_HW[RR * BB * OUTC];
__device__ float g_sum[RR][HID];
__device__ float g_sumsq[RR][HID];

// ---------------- helpers ----------------
__device__ __forceinline__ uint32_t smem_u32(const void* p) {
    uint32_t a;
    asm("{ .reg .u64 t; cvta.to.shared.u64 t, %1; cvt.u32.u64 %0, t; }"
        : "=r"(a) : "l"(p));
    return a;
}
__device__ __forceinline__ void ldsm_x4(uint32_t& r0, uint32_t& r1,
                                        uint32_t& r2, uint32_t& r3, uint32_t a) {
    asm volatile("ldmatrix.sync.aligned.m8n8.x4.shared.b16 {%0,%1,%2,%3}, [%4];"
                 : "=r"(r0), "=r"(r1), "=r"(r2), "=r"(r3) : "r"(a));
}
__device__ __forceinline__ void mma16816(float* d, const uint32_t* a,
                                         const uint32_t* b) {
    asm volatile(
        "mma.sync.aligned.m16n8k16.row.col.f32.bf16.bf16.f32 "
        "{%0,%1,%2,%3}, {%4,%5,%6,%7}, {%8,%9}, {%0,%1,%2,%3};"
        : "+f"(d[0]), "+f"(d[1]), "+f"(d[2]), "+f"(d[3])
        : "r"(a[0]), "r"(a[1]), "r"(a[2]), "r"(a[3]), "r"(b[0]), "r"(b[1]));
}
__device__ __forceinline__ void split2(float x, __nv_bfloat16& hi, __nv_bfloat16& lo) {
    hi = __float2bfloat16(x);
    lo = __float2bfloat16(x - __bfloat162float(hi));
}

// ---------------- setup ----------------
__global__ void k_init_pos() {
    int i = blockIdx.x * blockDim.x + threadIdx.x;
    if (i < NN) g_pos[i] = -1;
}
__global__ void k_set_pos(const int* __restrict__ bn) {
    int i = blockIdx.x * blockDim.x + threadIdx.x;
    if (i < BB) { int v = bn[i]; g_pos[v] = i; g_bn[i] = v; }
}
// clear per-relation state for ALL relations in one launch
__global__ void k_clear() {
    int i = blockIdx.x * blockDim.x + threadIdx.x;
    if (i < RR * BB) {
        int r = i / BB, j = i % BB;
        g_appear[r][j] = 0;
        g_deg[r][j] = 1.0f;
    }
    if (i < RR * HID) {
        int r = i / HID, c = i % HID;
        g_sum[r][c] = 0.0f;
        g_sumsq[r][c] = 0.0f;
    }
    if (i < RR) g_kept[i] = 0;
}

// ---------------- edge filtering, batched (grid.y = relation) ------------
__global__ void k_scan(const int4* __restrict__ ei4) {
    const int r = blockIdx.y;
    const int4* src4 = ei4 + (size_t)r * 2 * (EE / 4);
    const int4* dst4 = src4 + EE / 4;
    int i = blockIdx.x * blockDim.x + threadIdx.x;
    if (i >= EE / 4) return;
    int4 s = src4[i], d = dst4[i];
    int ss[4] = {s.x, s.y, s.z, s.w};
    int dd[4] = {d.x, d.y, d.z, d.w};
#pragma unroll
    for (int j = 0; j < 4; j++) {
        int ps = g_pos[ss[j]];
        int pd = g_pos[dd[j]];
        if ((ps | pd) >= 0) {
            g_appear[r][ps] = 1;
            g_appear[r][pd] = 1;
            int ix = atomicAdd(&g_kept[r], 1);
            g_ks[r][ix] = ps;
            g_kd[r][ix] = pd;
        }
    }
}

// 3 blocks, one per relation
__global__ void k_prefix() {
    const int r = blockIdx.x;
    __shared__ int ssum[256];
    int t = threadIdx.x;
    int base = t * 8;
    int v[8];
    int run = 0;
#pragma unroll
    for (int j = 0; j < 8; j++) { run += g_appear[r][base + j]; v[j] = run; }
    ssum[t] = run;
    __syncthreads();
    for (int off = 1; off < 256; off <<= 1) {
        int x = (t >= off) ? ssum[t - off] : 0;
        __syncthreads();
        ssum[t] += x;
        __syncthreads();
    }
    int pre = (t > 0) ? ssum[t - 1] : 0;
#pragma unroll
    for (int j = 0; j < 8; j++) g_rank[r][base + j] = pre + v[j] - 1;
}

__global__ void k_renum_deg() {
    const int r = blockIdx.y;
    int ne = g_kept[r];
    int stride = gridDim.x * blockDim.x;
    for (int e = blockIdx.x * blockDim.x + threadIdx.x; e < ne; e += stride) {
        int rs = g_rank[r][g_ks[r][e]];
        int rd = g_rank[r][g_kd[r][e]];
        g_ks[r][e] = rs;
        g_kd[r][e] = rd;
        atomicAdd(&g_deg[r][rd], 1.0f);
    }
}

// ---------------- bf16 split conversions ----------------
__global__ void k_convW1(const float* __restrict__ W1) {
    int idx = blockIdx.x * blockDim.x + threadIdx.x;  // HID*INP
    int n = idx >> 8, k = idx & (INP - 1);
    float x = W1[(size_t)k * HID + n];
    __nv_bfloat16 hi, lo; split2(x, hi, lo);
    size_t base = (size_t)n * K3_1;
    g_B1[base + k] = hi;
    g_B1[base + INP + k] = hi;
    g_B1[base + 2 * INP + k] = lo;
}
__global__ void k_convW2(const float* __restrict__ W2) {
    int idx = blockIdx.x * blockDim.x + threadIdx.x;  // OUTC*HID
    int n = idx >> 9, k = idx & (HID - 1);
    float x = W2[(size_t)k * OUTC + n];
    __nv_bfloat16 hi, lo; split2(x, hi, lo);
    size_t base = (size_t)n * K3_2;
    g_B2[base + k] = hi;
    g_B2[base + HID + k] = hi;
    g_B2[base + 2 * HID + k] = lo;
}
// features for all relations
__global__ void k_conv_feat(const float* __restrict__ feat) {
    int idx = blockIdx.x * blockDim.x + threadIdx.x;  // RR*BB*INP
    int c = idx & (INP - 1);
    int i = (idx >> 8) & (BB - 1);
    int r = idx >> 19;                 // / (BB*INP)
    float x = feat[((size_t)r * NN + g_bn[i]) * INP + c];
    __nv_bfloat16 hi, lo; split2(x, hi, lo);
    size_t base = ((size_t)r * BB + i) * K3_1;
    g_A1[base + c] = hi;
    g_A1[base + INP + c] = lo;
    g_A1[base + 2 * INP + c] = hi;
}

// BN stats (batched)
__global__ void k_bn_stats() {
    const int r = blockIdx.y;
    int c = threadIdx.x;  // 512
    int r0 = blockIdx.x * 32;
    const float* base = g_AGG + (size_t)r * BB * HID;
    float s = 0.0f, s2 = 0.0f;
#pragma unroll 4
    for (int i = 0; i < 32; i++) {
        float v = base[(size_t)(r0 + i) * HID + c];
        s += v;
        s2 += v * v;
    }
    atomicAdd(&g_sum[r][c], s);
    atomicAdd(&g_sumsq[r][c], s2);
}

// BN normalize + bf16 split (scale/shift computed inline; k_bn_final fused away)
__global__ void k_bn_norm_conv(const float* __restrict__ gamma,
                               const float* __restrict__ beta) {
    int idx = blockIdx.x * blockDim.x + threadIdx.x;  // RR*BB*HID
    int c = idx & (HID - 1);
    int i = (idx >> 9) & (BB - 1);
    int r = idx >> 20;                 // / (BB*HID)
    const float inv = 1.0f / (float)BB;
    float mu = g_sum[r][c] * inv;
    float var = g_sumsq[r][c] * inv - mu * mu;
    float sc = rsqrtf(var + BN_EPS) * gamma[c];
    float sh = beta[c] - mu * sc;
    float h = g_AGG[idx] * sc + sh;
    __nv_bfloat16 hi, lo; split2(h, hi, lo);
    size_t base = ((size_t)r * BB + i) * K3_2;
    g_A2[base + c] = hi;
    g_A2[base + HID + c] = lo;
    g_A2[base + 2 * HID + c] = hi;
}

// ---------------- HMMA GEMM (batched over relations via blockIdx.z) -------
template <int K3, int NTOT, int NTILE, int EPI>
__device__ __forceinline__ void hmma_body(const __nv_bfloat16* __restrict__ Aall,
                                          const __nv_bfloat16* __restrict__ BT,
                                          float* __restrict__ outall,
                                          const float* __restrict__ b2) {
    constexpr int NW = NTILE / 2;
    constexpr int NF = NW / 8;
    __shared__ alignas(1024) __nv_bfloat16 sA[128 * 64];
    __shared__ alignas(1024) __nv_bfloat16 sB[NTILE * 64];

    const int tid = threadIdx.x, wid = tid >> 5, lid = tid & 31;
    const int mwarp = wid & 3, nwarp = wid >> 2;
    const int rel = blockIdx.z;
    const int m0 = blockIdx.y * 128, n0 = blockIdx.x * NTILE;
    const __nv_bfloat16* A = Aall + (size_t)rel * BB * K3;
    const uint32_t sA0 = smem_u32(sA), sB0 = smem_u32(sB);

    float acc[2][NF][4];
#pragma unroll
    for (int mi = 0; mi < 2; mi++)
#pragma unroll
        for (int nf = 0; nf < NF; nf++)
#pragma unroll
            for (int j = 0; j < 4; j++) acc[mi][nf][j] = 0.0f;

    const int a_row = lid & 15, a_kb = (lid >> 4) * 16;
    const int b_nn = ((lid >> 4) << 3) + (lid & 7), b_kb = ((lid >> 3) & 1) * 16;

    for (int kc = 0; kc < K3; kc += 64) {
#pragma unroll
        for (int it = 0; it < 4; it++) {
            int idx = it * 256 + tid;
            int r = idx >> 3, c16 = idx & 7;
            uint32_t byte = (uint32_t)(r * 128 + c16 * 16);
            uint32_t sw = byte ^ ((byte >> 3) & 0x70);
            *(uint4*)((char*)sA + sw) =
                *(const uint4*)(A + (size_t)(m0 + r) * K3 + kc + c16 * 8);
        }
#pragma unroll
        for (int it = 0; it < NTILE / 32; it++) {
            int idx = it * 256 + tid;
            int r = idx >> 3, c16 = idx & 7;
            uint32_t byte = (uint32_t)(r * 128 + c16 * 16);
            uint32_t sw = byte ^ ((byte >> 3) & 0x70);
            *(uint4*)((char*)sB + sw) =
                *(const uint4*)(BT + (size_t)(n0 + r) * K3 + kc + c16 * 8);
        }
        __syncthreads();
#pragma unroll
        for (int ks = 0; ks < 4; ks++) {
            const int kbyte = ks * 32;
            uint32_t af[2][4];
#pragma unroll
            for (int mi = 0; mi < 2; mi++) {
                int row = mwarp * 32 + mi * 16 + a_row;
                uint32_t byte = (uint32_t)(row * 128 + kbyte + a_kb);
                uint32_t sw = byte ^ ((byte >> 3) & 0x70);
                ldsm_x4(af[mi][0], af[mi][1], af[mi][2], af[mi][3], sA0 + sw);
            }
            uint32_t bf_[NF][2];
#pragma unroll
            for (int np = 0; np < NF / 2; np++) {
                int nn = nwarp * NW + np * 16 + b_nn;
                uint32_t byte = (uint32_t)(nn * 128 + kbyte + b_kb);
                uint32_t sw = byte ^ ((byte >> 3) & 0x70);
                uint32_t r0, r1, r2, r3;
                ldsm_x4(r0, r1, r2, r3, sB0 + sw);
                bf_[2 * np][0] = r0; bf_[2 * np][1] = r1;
                bf_[2 * np + 1][0] = r2; bf_[2 * np + 1][1] = r3;
            }
#pragma unroll
            for (int mi = 0; mi < 2; mi++)
#pragma unroll
                for (int nf = 0; nf < NF; nf++)
                    mma16816(acc[mi][nf], af[mi], bf_[nf]);
        }
        __syncthreads();
    }

    const int gid = lid >> 2, tg = lid & 3;
#pragma unroll
    for (int mi = 0; mi < 2; mi++) {
        const int rA = m0 + mwarp * 32 + mi * 16 + gid;
        const int rB = rA + 8;
        const float d2A = 1.0f / g_deg[rel][rA];   // dinv^2 == 1/deg
        const float d2B = 1.0f / g_deg[rel][rB];
#pragma unroll
        for (int nf = 0; nf < NF; nf++) {
            const int c = n0 + nwarp * NW + nf * 8 + tg * 2;
            float2 vA = make_float2(acc[mi][nf][0], acc[mi][nf][1]);
            float2 vB = make_float2(acc[mi][nf][2], acc[mi][nf][3]);
            size_t offA = ((size_t)rel * BB + rA) * NTOT + c;
            size_t offB = ((size_t)rel * BB + rB) * NTOT + c;
            if (EPI == 0) {
                *(float2*)(g_XW + offA) = vA;
                *(float2*)(g_XW + offB) = vB;
                *(float2*)(g_AGG + offA) = make_float2(d2A * vA.x, d2A * vA.y);
                *(float2*)(g_AGG + offB) = make_float2(d2B * vB.x, d2B * vB.y);
            } else {
                *(float2*)(g_HW + offA) = vA;
                *(float2*)(g_HW + offB) = vB;
                float2 bb = *(const float2*)(b2 + c);
                *(float2*)(outall + offA) =
                    make_float2(d2A * vA.x + bb.x, d2A * vA.y + bb.y);
                *(float2*)(outall + offB) =
                    make_float2(d2B * vB.x + bb.x, d2B * vB.y + bb.y);
            }
        }
    }
}

__global__ void __launch_bounds__(256)
k_mma1() { hmma_body<K3_1, HID, 128, 0>(g_A1, g_B1, nullptr, nullptr); }

__global__ void __launch_bounds__(256)
k_mma2(float* __restrict__ outp, const float* __restrict__ b2) {
    hmma_body<K3_2, OUTC, 64, 1>(g_A2, g_B2, outp, b2);
}

// ---------------- edge scatter (batched) ----------------
__global__ void k_agg_edges_h() {
    const int r = blockIdx.y;
    int ne = g_kept[r];
    const float* S = g_XW + (size_t)r * BB * HID;
    float* D = g_AGG + (size_t)r * BB * HID;
    for (int e = blockIdx.x; e < ne; e += gridDim.x) {
        int s = g_ks[r][e], d = g_kd[r][e];
        float coeff = rsqrtf(g_deg[r][s] * g_deg[r][d]);
        const float* sp = S + (size_t)s * HID;
        float* dp = D + (size_t)d * HID;
        for (int c = threadIdx.x; c < HID; c += blockDim.x)
            atomicAdd(&dp[c], coeff * sp[c]);
    }
}
__global__ void k_agg_edges_o(float* __restrict__ outp) {
    const int r = blockIdx.y;
    int ne = g_kept[r];
    const float* S = g_HW + (size_t)r * BB * OUTC;
    float* D = outp + (size_t)r * BB * OUTC;
    for (int e = blockIdx.x; e < ne; e += gridDim.x) {
        int s = g_ks[r][e], d = g_kd[r][e];
        float coeff = rsqrtf(g_deg[r][s] * g_deg[r][d]);
        const float* sp = S + (size_t)s * OUTC;
        float* dp = D + (size_t)d * OUTC;
        for (int c = threadIdx.x; c < OUTC; c += blockDim.x)
            atomicAdd(&dp[c], coeff * sp[c]);
    }
}

// ---------------- host launch ----------------
extern "C" void kernel_launch(void* const* d_in, const int* in_sizes, int n_in,
                              void* d_out, int out_size) {
    const float* feat = (const float*)d_in[0];
    const float* W1 = (const float*)d_in[1];
    // b1 (d_in[2]) cancels inside BatchNorm -> unused
    const float* W2 = (const float*)d_in[3];
    const float* b2 = (const float*)d_in[4];
    const float* gamma = (const float*)d_in[5];
    const float* beta = (const float*)d_in[6];
    const int* ei = (const int*)d_in[7];
    const int* bn = (const int*)d_in[8];
    float* out = (float*)d_out;

    k_init_pos<<<(NN + 255) / 256, 256>>>();
    k_set_pos<<<(BB + 255) / 256, 256>>>(bn);
    k_convW1<<<HID * INP / 256, 256>>>(W1);
    k_convW2<<<OUTC * HID / 256, 256>>>(W2);
    k_clear<<<(RR * BB + 255) / 256, 256>>>();

    { dim3 g((EE / 4 + 255) / 256, RR); k_scan<<<g, 256>>>((const int4*)ei); }
    k_prefix<<<RR, 256>>>();
    { dim3 g(256, RR); k_renum_deg<<<g, 256>>>(); }
    k_conv_feat<<<RR * BB * INP / 256, 256>>>(feat);

    { dim3 g(HID / 128, BB / 128, RR); k_mma1<<<g, 256>>>(); }
    { dim3 g(1024, RR); k_agg_edges_h<<<g, 128>>>(); }

    { dim3 g(BB / 32, RR); k_bn_stats<<<g, 512>>>(); }
    k_bn_norm_conv<<<RR * BB * HID / 256, 256>>>(gamma, beta);

    { dim3 g(OUTC / 64, BB / 128, RR); k_mma2<<<g, 256>>>(out, b2); }
    { dim3 g(1024, RR); k_agg_edges_o<<<g, 128>>>(out); }
}

// round 7
// speedup vs baseline: 2.1131x; 1.0135x over previous
#include <cuda_runtime.h>
#include <cuda_bf16.h>
#include <cstdint>

#define NN   50000
#define EE   1000000
#define BB   2048
#define RR   3
#define INP  256
#define HID  512
#define OUTC 256
#define BN_EPS 1e-5f
#define K3_1 (3*INP)    // 768
#define K3_2 (3*HID)    // 1536

// ---------------- device scratch ----------------
__device__ int   g_pos[NN];
__device__ int   g_appear[RR][BB];
__device__ float g_deg[RR][BB];
__device__ int   g_kept[RR];
__device__ int   g_ks[RR][EE];
__device__ int   g_kd[RR][EE];
__device__ __align__(16) __nv_bfloat16 g_A1[RR * BB * K3_1];
__device__ __align__(16) __nv_bfloat16 g_B1[HID * K3_1];
__device__ __align__(16) __nv_bfloat16 g_A2[RR * BB * K3_2];
__device__ __align__(16) __nv_bfloat16 g_B2[OUTC * K3_2];
__device__ __align__(16) float g_XW[RR * BB * HID];
__device__ __align__(16) float g_AGG[RR * BB * HID];   // edge-scatter accumulator (zeroed)
__device__ __align__(16) float g_HW[RR * BB * OUTC];
__device__ float g_sum[RR][HID];
__device__ float g_sumsq[RR][HID];

// ---------------- helpers ----------------
__device__ __forceinline__ uint32_t smem_u32(const void* p) {
    uint32_t a;
    asm("{ .reg .u64 t; cvta.to.shared.u64 t, %1; cvt.u32.u64 %0, t; }"
        : "=r"(a) : "l"(p));
    return a;
}
__device__ __forceinline__ void ldsm_x4(uint32_t& r0, uint32_t& r1,
                                        uint32_t& r2, uint32_t& r3, uint32_t a) {
    asm volatile("ldmatrix.sync.aligned.m8n8.x4.shared.b16 {%0,%1,%2,%3}, [%4];"
                 : "=r"(r0), "=r"(r1), "=r"(r2), "=r"(r3) : "r"(a));
}
__device__ __forceinline__ void mma16816(float* d, const uint32_t* a,
                                         const uint32_t* b) {
    asm volatile(
        "mma.sync.aligned.m16n8k16.row.col.f32.bf16.bf16.f32 "
        "{%0,%1,%2,%3}, {%4,%5,%6,%7}, {%8,%9}, {%0,%1,%2,%3};"
        : "+f"(d[0]), "+f"(d[1]), "+f"(d[2]), "+f"(d[3])
        : "r"(a[0]), "r"(a[1]), "r"(a[2]), "r"(a[3]), "r"(b[0]), "r"(b[1]));
}
__device__ __forceinline__ void split2(float x, __nv_bfloat16& hi, __nv_bfloat16& lo) {
    hi = __float2bfloat16(x);
    lo = __float2bfloat16(x - __bfloat162float(hi));
}

// ---------------- fused prologue ----------------
// Zeros AGG/sums/appear/kept, inits pos table, converts W1/W2 to split bf16.
__global__ void k_pre(const float* __restrict__ W1, const float* __restrict__ W2) {
    int idx = blockIdx.x * blockDim.x + threadIdx.x;   // grid covers RR*BB*HID/4
    if (idx < RR * BB * HID / 4)
        ((float4*)g_AGG)[idx] = make_float4(0.f, 0.f, 0.f, 0.f);
    if (idx < NN) g_pos[idx] = -1;
    if (idx < RR * BB) ((int*)g_appear)[idx] = 0;
    if (idx < RR * HID) { ((float*)g_sum)[idx] = 0.f; ((float*)g_sumsq)[idx] = 0.f; }
    if (idx < RR) g_kept[idx] = 0;
    if (idx < HID * INP) {
        int n = idx >> 8, k = idx & (INP - 1);
        __nv_bfloat16 hi, lo; split2(W1[(size_t)k * HID + n], hi, lo);
        size_t base = (size_t)n * K3_1;
        g_B1[base + k] = hi;
        g_B1[base + INP + k] = hi;
        g_B1[base + 2 * INP + k] = lo;
    }
    if (idx < OUTC * HID) {
        int n = idx >> 9, k = idx & (HID - 1);
        __nv_bfloat16 hi, lo; split2(W2[(size_t)k * OUTC + n], hi, lo);
        size_t base = (size_t)n * K3_2;
        g_B2[base + k] = hi;
        g_B2[base + HID + k] = hi;
        g_B2[base + 2 * HID + k] = lo;
    }
}

__global__ void k_set_pos(const int* __restrict__ bn) {
    int i = blockIdx.x * blockDim.x + threadIdx.x;
    if (i < BB) g_pos[bn[i]] = i;
}

// ---------------- edge filtering (batched) ----------------
__global__ void k_scan(const int4* __restrict__ ei4) {
    const int r = blockIdx.y;
    const int4* src4 = ei4 + (size_t)r * 2 * (EE / 4);
    const int4* dst4 = src4 + EE / 4;
    int i = blockIdx.x * blockDim.x + threadIdx.x;
    if (i >= EE / 4) return;
    int4 s = src4[i], d = dst4[i];
    int ss[4] = {s.x, s.y, s.z, s.w};
    int dd[4] = {d.x, d.y, d.z, d.w};
#pragma unroll
    for (int j = 0; j < 4; j++) {
        int ps = g_pos[ss[j]];
        int pd = g_pos[dd[j]];
        if ((ps | pd) >= 0) {
            g_appear[r][ps] = 1;
            g_appear[r][pd] = 1;
            int ix = atomicAdd(&g_kept[r], 1);
            g_ks[r][ix] = ps;
            g_kd[r][ix] = pd;
        }
    }
}

// prefix scan + renumber + degree, one block per relation (1024 threads)
__global__ void __launch_bounds__(1024)
k_prefix_renum() {
    const int r = blockIdx.x;
    const int t = threadIdx.x;
    __shared__ int sc[1024];
    __shared__ int srank[BB];
    __shared__ float sdeg[BB];
    int a0 = g_appear[r][2 * t], a1 = g_appear[r][2 * t + 1];
    sc[t] = a0 + a1;
    sdeg[2 * t] = 0.f;
    sdeg[2 * t + 1] = 0.f;
    __syncthreads();
    for (int off = 1; off < 1024; off <<= 1) {
        int x = (t >= off) ? sc[t - off] : 0;
        __syncthreads();
        sc[t] += x;
        __syncthreads();
    }
    int pre = (t > 0) ? sc[t - 1] : 0;
    srank[2 * t] = pre + a0 - 1;
    srank[2 * t + 1] = pre + a0 + a1 - 1;
    __syncthreads();
    int ne = g_kept[r];
    for (int e = t; e < ne; e += 1024) {
        int rs = srank[g_ks[r][e]];
        int rd = srank[g_kd[r][e]];
        g_ks[r][e] = rs;
        g_kd[r][e] = rd;
        atomicAdd(&sdeg[rd], 1.0f);
    }
    __syncthreads();
    g_deg[r][2 * t] = 1.0f + sdeg[2 * t];
    g_deg[r][2 * t + 1] = 1.0f + sdeg[2 * t + 1];
}

// ---------------- feature conversion (reads bn directly; no set_pos dep) ----
__global__ void k_conv_feat(const float* __restrict__ feat, const int* __restrict__ bn) {
    int idx = blockIdx.x * blockDim.x + threadIdx.x;  // RR*BB*INP
    int c = idx & (INP - 1);
    int i = (idx >> 8) & (BB - 1);
    int r = idx >> 19;
    float x = feat[((size_t)r * NN + bn[i]) * INP + c];
    __nv_bfloat16 hi, lo; split2(x, hi, lo);
    size_t base = ((size_t)r * BB + i) * K3_1;
    g_A1[base + c] = hi;
    g_A1[base + INP + c] = lo;
    g_A1[base + 2 * INP + c] = hi;
}

// ---------------- HMMA GEMM (batched over relations) ----------------------
// EPI=0: write XW only.  EPI=1: write HW and out = HW/deg + b2.
template <int K3, int NTOT, int NTILE, int EPI>
__device__ __forceinline__ void hmma_body(const __nv_bfloat16* __restrict__ Aall,
                                          const __nv_bfloat16* __restrict__ BT,
                                          float* __restrict__ outall,
                                          const float* __restrict__ b2) {
    constexpr int NW = NTILE / 2;
    constexpr int NF = NW / 8;
    __shared__ alignas(1024) __nv_bfloat16 sA[128 * 64];
    __shared__ alignas(1024) __nv_bfloat16 sB[NTILE * 64];

    const int tid = threadIdx.x, wid = tid >> 5, lid = tid & 31;
    const int mwarp = wid & 3, nwarp = wid >> 2;
    const int rel = blockIdx.z;
    const int m0 = blockIdx.y * 128, n0 = blockIdx.x * NTILE;
    const __nv_bfloat16* A = Aall + (size_t)rel * BB * K3;
    const uint32_t sA0 = smem_u32(sA), sB0 = smem_u32(sB);

    float acc[2][NF][4];
#pragma unroll
    for (int mi = 0; mi < 2; mi++)
#pragma unroll
        for (int nf = 0; nf < NF; nf++)
#pragma unroll
            for (int j = 0; j < 4; j++) acc[mi][nf][j] = 0.0f;

    const int a_row = lid & 15, a_kb = (lid >> 4) * 16;
    const int b_nn = ((lid >> 4) << 3) + (lid & 7), b_kb = ((lid >> 3) & 1) * 16;

    for (int kc = 0; kc < K3; kc += 64) {
#pragma unroll
        for (int it = 0; it < 4; it++) {
            int idx = it * 256 + tid;
            int r = idx >> 3, c16 = idx & 7;
            uint32_t byte = (uint32_t)(r * 128 + c16 * 16);
            uint32_t sw = byte ^ ((byte >> 3) & 0x70);
            *(uint4*)((char*)sA + sw) =
                *(const uint4*)(A + (size_t)(m0 + r) * K3 + kc + c16 * 8);
        }
#pragma unroll
        for (int it = 0; it < NTILE / 32; it++) {
            int idx = it * 256 + tid;
            int r = idx >> 3, c16 = idx & 7;
            uint32_t byte = (uint32_t)(r * 128 + c16 * 16);
            uint32_t sw = byte ^ ((byte >> 3) & 0x70);
            *(uint4*)((char*)sB + sw) =
                *(const uint4*)(BT + (size_t)(n0 + r) * K3 + kc + c16 * 8);
        }
        __syncthreads();
#pragma unroll
        for (int ks = 0; ks < 4; ks++) {
            const int kbyte = ks * 32;
            uint32_t af[2][4];
#pragma unroll
            for (int mi = 0; mi < 2; mi++) {
                int row = mwarp * 32 + mi * 16 + a_row;
                uint32_t byte = (uint32_t)(row * 128 + kbyte + a_kb);
                uint32_t sw = byte ^ ((byte >> 3) & 0x70);
                ldsm_x4(af[mi][0], af[mi][1], af[mi][2], af[mi][3], sA0 + sw);
            }
            uint32_t bf_[NF][2];
#pragma unroll
            for (int np = 0; np < NF / 2; np++) {
                int nn = nwarp * NW + np * 16 + b_nn;
                uint32_t byte = (uint32_t)(nn * 128 + kbyte + b_kb);
                uint32_t sw = byte ^ ((byte >> 3) & 0x70);
                uint32_t r0, r1, r2, r3;
                ldsm_x4(r0, r1, r2, r3, sB0 + sw);
                bf_[2 * np][0] = r0; bf_[2 * np][1] = r1;
                bf_[2 * np + 1][0] = r2; bf_[2 * np + 1][1] = r3;
            }
#pragma unroll
            for (int mi = 0; mi < 2; mi++)
#pragma unroll
                for (int nf = 0; nf < NF; nf++)
                    mma16816(acc[mi][nf], af[mi], bf_[nf]);
        }
        __syncthreads();
    }

    const int gid = lid >> 2, tg = lid & 3;
#pragma unroll
    for (int mi = 0; mi < 2; mi++) {
        const int rA = m0 + mwarp * 32 + mi * 16 + gid;
        const int rB = rA + 8;
        float d2A = 0.f, d2B = 0.f;
        if (EPI == 1) { d2A = 1.0f / g_deg[rel][rA]; d2B = 1.0f / g_deg[rel][rB]; }
#pragma unroll
        for (int nf = 0; nf < NF; nf++) {
            const int c = n0 + nwarp * NW + nf * 8 + tg * 2;
            float2 vA = make_float2(acc[mi][nf][0], acc[mi][nf][1]);
            float2 vB = make_float2(acc[mi][nf][2], acc[mi][nf][3]);
            size_t offA = ((size_t)rel * BB + rA) * NTOT + c;
            size_t offB = ((size_t)rel * BB + rB) * NTOT + c;
            if (EPI == 0) {
                *(float2*)(g_XW + offA) = vA;
                *(float2*)(g_XW + offB) = vB;
            } else {
                *(float2*)(g_HW + offA) = vA;
                *(float2*)(g_HW + offB) = vB;
                float2 bb = *(const float2*)(b2 + c);
                *(float2*)(outall + offA) =
                    make_float2(d2A * vA.x + bb.x, d2A * vA.y + bb.y);
                *(float2*)(outall + offB) =
                    make_float2(d2B * vB.x + bb.x, d2B * vB.y + bb.y);
            }
        }
    }
}

__global__ void __launch_bounds__(256)
k_mma1() { hmma_body<K3_1, HID, 128, 0>(g_A1, g_B1, nullptr, nullptr); }

__global__ void __launch_bounds__(256)
k_mma2(float* __restrict__ outp, const float* __restrict__ b2) {
    hmma_body<K3_2, OUTC, 64, 1>(g_A2, g_B2, outp, b2);
}

// ---------------- edge scatter ----------------
__global__ void k_agg_edges_h() {
    const int r = blockIdx.y;
    int ne = g_kept[r];
    const float* S = g_XW + (size_t)r * BB * HID;
    float* D = g_AGG + (size_t)r * BB * HID;
    for (int e = blockIdx.x; e < ne; e += gridDim.x) {
        int s = g_ks[r][e], d = g_kd[r][e];
        float coeff = rsqrtf(g_deg[r][s] * g_deg[r][d]);
        const float* sp = S + (size_t)s * HID;
        float* dp = D + (size_t)d * HID;
        for (int c = threadIdx.x; c < HID; c += blockDim.x)
            atomicAdd(&dp[c], coeff * sp[c]);
    }
}
__global__ void k_agg_edges_o(float* __restrict__ outp) {
    const int r = blockIdx.y;
    int ne = g_kept[r];
    const float* S = g_HW + (size_t)r * BB * OUTC;
    float* D = outp + (size_t)r * BB * OUTC;
    for (int e = blockIdx.x; e < ne; e += gridDim.x) {
        int s = g_ks[r][e], d = g_kd[r][e];
        float coeff = rsqrtf(g_deg[r][s] * g_deg[r][d]);
        const float* sp = S + (size_t)s * OUTC;
        float* dp = outp == D ? D + (size_t)d * OUTC : D + (size_t)d * OUTC;
        float* dpp = D + (size_t)d * OUTC;
        (void)dp;
        for (int c = threadIdx.x; c < OUTC; c += blockDim.x)
            atomicAdd(&dpp[c], coeff * sp[c]);
    }
}

// ---------------- batchnorm (self-loop term fused: h = AGG + XW/deg) ------
__global__ void k_bn_stats() {
    const int r = blockIdx.y;
    int c = threadIdx.x;  // 512
    int r0 = blockIdx.x * 32;
    const float* agg = g_AGG + (size_t)r * BB * HID;
    const float* xw = g_XW + (size_t)r * BB * HID;
    float s = 0.0f, s2 = 0.0f;
#pragma unroll 4
    for (int i = 0; i < 32; i++) {
        float inv = 1.0f / g_deg[r][r0 + i];
        float v = agg[(size_t)(r0 + i) * HID + c] + inv * xw[(size_t)(r0 + i) * HID + c];
        s += v;
        s2 += v * v;
    }
    atomicAdd(&g_sum[r][c], s);
    atomicAdd(&g_sumsq[r][c], s2);
}

__global__ void k_bn_norm_conv(const float* __restrict__ gamma,
                               const float* __restrict__ beta) {
    int idx = blockIdx.x * blockDim.x + threadIdx.x;  // RR*BB*HID
    int c = idx & (HID - 1);
    int i = (idx >> 9) & (BB - 1);
    int r = idx >> 20;
    const float invB = 1.0f / (float)BB;
    float mu = g_sum[r][c] * invB;
    float var = g_sumsq[r][c] * invB - mu * mu;
    float sc = rsqrtf(var + BN_EPS) * gamma[c];
    float sh = beta[c] - mu * sc;
    float h = (g_AGG[idx] + g_XW[idx] / g_deg[r][i]) * sc + sh;
    __nv_bfloat16 hi, lo; split2(h, hi, lo);
    size_t base = ((size_t)r * BB + i) * K3_2;
    g_A2[base + c] = hi;
    g_A2[base + HID + c] = lo;
    g_A2[base + 2 * HID + c] = hi;
}

// ---------------- host launch ----------------
extern "C" void kernel_launch(void* const* d_in, const int* in_sizes, int n_in,
                              void* d_out, int out_size) {
    const float* feat = (const float*)d_in[0];
    const float* W1 = (const float*)d_in[1];
    // b1 cancels in BatchNorm
    const float* W2 = (const float*)d_in[3];
    const float* b2 = (const float*)d_in[4];
    const float* gamma = (const float*)d_in[5];
    const float* beta = (const float*)d_in[6];
    const int* ei = (const int*)d_in[7];
    const int* bn = (const int*)d_in[8];
    float* out = (float*)d_out;

    static cudaStream_t s_side = nullptr;
    static cudaEvent_t ev_fork = nullptr, ev_join = nullptr;
    if (!s_side) {
        cudaStreamCreateWithFlags(&s_side, cudaStreamNonBlocking);
        cudaEventCreateWithFlags(&ev_fork, cudaEventDisableTiming);
        cudaEventCreateWithFlags(&ev_join, cudaEventDisableTiming);
    }

    // prologue on main stream
    k_pre<<<RR * BB * HID / 4 / 256, 256>>>(W1, W2);

    // fork: edge path on side stream
    cudaEventRecord(ev_fork, 0);
    cudaStreamWaitEvent(s_side, ev_fork, 0);
    k_set_pos<<<(BB + 255) / 256, 256, 0, s_side>>>(bn);
    { dim3 g((EE / 4 + 255) / 256, RR); k_scan<<<g, 256, 0, s_side>>>((const int4*)ei); }
    k_prefix_renum<<<RR, 1024, 0, s_side>>>();
    cudaEventRecord(ev_join, s_side);

    // compute path on main stream (no dependency on edge path)
    k_conv_feat<<<RR * BB * INP / 256, 256>>>(feat, bn);
    { dim3 g(HID / 128, BB / 128, RR); k_mma1<<<g, 256>>>(); }

    // join
    cudaStreamWaitEvent(0, ev_join, 0);

    { dim3 g(512, RR); k_agg_edges_h<<<g, 128>>>(); }
    { dim3 g(BB / 32, RR); k_bn_stats<<<g, 512>>>(); }
    k_bn_norm_conv<<<RR * BB * HID / 256, 256>>>(gamma, beta);
    { dim3 g(OUTC / 64, BB / 128, RR); k_mma2<<<g, 256>>>(out, b2); }
    { dim3 g(512, RR); k_agg_edges_o<<<g, 128>>>(out); }
}